// round 1
// baseline (speedup 1.0000x reference)
#include <cuda_runtime.h>
#include <cuda_bf16.h>

// Token-conditioned hidden-state table: hs depends only on token id (V=64).
__device__ float g_hs_table[64 * 64];

#define H      64
#define VOCAB  64
#define INNER  16
#define LSEQ   2048
#define TSTEPS 1023
#define LRATE  0.01f
#define C2H    (2.0f / 64.0f)

// ---------------------------------------------------------------------------
// Kernel A: build hs_table[v][h] = LayerNorm(e + FF(e)) for each vocab id v.
// grid(64), block(128)
// ---------------------------------------------------------------------------
__global__ void build_table_kernel(
    const float* __restrict__ embed,   // (64,64)
    const float* __restrict__ ff_w1,   // (64,128)
    const float* __restrict__ ff_b1,   // (128,)
    const float* __restrict__ ff_w2,   // (128,64)
    const float* __restrict__ ff_b2,   // (64,)
    const float* __restrict__ ln_g,    // (64,)
    const float* __restrict__ ln_b)    // (64,)
{
    __shared__ float e_sh[64];
    __shared__ float u_sh[128];
    __shared__ float h_sh[64];

    const int v = blockIdx.x;
    const int t = threadIdx.x;

    if (t < 64) e_sh[t] = embed[v * 64 + t];
    __syncthreads();

    // u = relu(e @ ff_w1 + ff_b1), 128-wide
    {
        float acc = ff_b1[t];
        #pragma unroll 8
        for (int h = 0; h < 64; ++h)
            acc = fmaf(e_sh[h], ff_w1[h * 128 + t], acc);
        u_sh[t] = fmaxf(acc, 0.0f);
    }
    __syncthreads();

    // h = e + u @ ff_w2 + ff_b2, 64-wide
    if (t < 64) {
        float acc = ff_b2[t];
        #pragma unroll 8
        for (int i = 0; i < 128; ++i)
            acc = fmaf(u_sh[i], ff_w2[i * 64 + t], acc);
        h_sh[t] = e_sh[t] + acc;
    }
    __syncthreads();

    // LayerNorm over H=64 (redundant per-thread reduction; one-time cost)
    if (t < 64) {
        float mu = 0.0f;
        #pragma unroll 8
        for (int h = 0; h < 64; ++h) mu += h_sh[h];
        mu *= (1.0f / 64.0f);
        float var = 0.0f;
        #pragma unroll 8
        for (int h = 0; h < 64; ++h) {
            float d = h_sh[h] - mu;
            var = fmaf(d, d, var);
        }
        var *= (1.0f / 64.0f);
        const float inv = rsqrtf(var + 1e-5f);
        g_hs_table[v * 64 + t] = (h_sh[t] - mu) * inv * ln_g[t] + ln_b[t];
    }
}

// ---------------------------------------------------------------------------
// Kernel B: per-batch TTT chain. One warp per batch element.
// Lane t owns h-rows {t, t+32}: W1 rows (2x16), W2 cols (2x16) in registers.
// grid(256), block(32)
// ---------------------------------------------------------------------------
__global__ void __launch_bounds__(32, 8) ttt_kernel(
    const int*   __restrict__ seq,     // (256, 2048) int32
    const float* __restrict__ w1,      // (64,16)
    const float* __restrict__ b1,      // (16,)
    const float* __restrict__ w2,      // (16,64)
    const float* __restrict__ b2,      // (64,)
    const float* __restrict__ out_w,   // (64,64)
    const float* __restrict__ out_b,   // (64,)
    float*       __restrict__ out)     // (256,64)
{
    __shared__ float tab[VOCAB * H];   // 16 KB
    __shared__ int   toks[LSEQ];       // 8 KB
    __shared__ float ctx_sh[H];

    const int b = blockIdx.x;
    const int t = threadIdx.x;

    // Stage table + this batch's token row into SMEM
    for (int i = t; i < VOCAB * H; i += 32) tab[i] = g_hs_table[i];
    const int* srow = seq + b * LSEQ;
    for (int i = t; i < LSEQ; i += 32) toks[i] = srow[i];

    // Load initial parameters (shared p0 across batches)
    float W1a[INNER], W1b[INNER], W2a[INNER], W2b[INNER], b1r[INNER];
    #pragma unroll
    for (int j = 0; j < INNER; ++j) {
        W1a[j] = w1[t * INNER + j];
        W1b[j] = w1[(t + 32) * INNER + j];
        W2a[j] = w2[j * H + t];
        W2b[j] = w2[j * H + t + 32];
        b1r[j] = b1[j];
    }
    float b2a = b2[t];
    float b2b = b2[t + 32];

    __syncthreads();

    float a[INNER], p[INNER];

    #pragma unroll 1
    for (int s = 0; s < TSTEPS; ++s) {
        const int tk = toks[2 * s];
        const int tv = toks[2 * s + 1];
        const float k0 = tab[tk * H + t];
        const float k1 = tab[tk * H + t + 32];
        const float v0 = tab[tv * H + t];
        const float v1 = tab[tv * H + t + 32];

        // ---- forward: z[j] = b1[j] + sum_h k[h] W1[h,j] (cross-lane reduce) ----
        #pragma unroll
        for (int j = 0; j < INNER; ++j)
            p[j] = fmaf(k0, W1a[j], k1 * W1b[j]);
        #pragma unroll
        for (int st = 16; st >= 1; st >>= 1) {
            #pragma unroll
            for (int j = 0; j < INNER; ++j)
                p[j] += __shfl_xor_sync(0xffffffffu, p[j], st);
        }
        #pragma unroll
        for (int j = 0; j < INNER; ++j)
            a[j] = fmaxf(p[j] + b1r[j], 0.0f);   // a>0 <=> z>0 (relu mask)

        // ---- pred[h] = b2[h] + sum_j a[j] W2[j,h] (lane-local, 2 accums) ----
        float pr0 = b2a, pr0x = 0.0f, pr1 = b2b, pr1x = 0.0f;
        #pragma unroll
        for (int j = 0; j < INNER; j += 2) {
            pr0  = fmaf(a[j],     W2a[j],     pr0);
            pr0x = fmaf(a[j + 1], W2a[j + 1], pr0x);
            pr1  = fmaf(a[j],     W2b[j],     pr1);
            pr1x = fmaf(a[j + 1], W2b[j + 1], pr1x);
        }
        const float d0 = C2H * ((pr0 + pr0x) - v0);
        const float d1 = C2H * ((pr1 + pr1x) - v1);

        // ---- da[j] = sum_h d[h] W2_old[j,h] (cross-lane reduce, BEFORE W2 update) ----
        #pragma unroll
        for (int j = 0; j < INNER; ++j)
            p[j] = fmaf(d0, W2a[j], d1 * W2b[j]);
        #pragma unroll
        for (int st = 16; st >= 1; st >>= 1) {
            #pragma unroll
            for (int j = 0; j < INNER; ++j)
                p[j] += __shfl_xor_sync(0xffffffffu, p[j], st);
        }

        // ---- update W2, b2: dW2[j,h] = a[j]*d[h] ----
        const float l0 = LRATE * d0;
        const float l1 = LRATE * d1;
        #pragma unroll
        for (int j = 0; j < INNER; ++j) {
            W2a[j] = fmaf(-l0, a[j], W2a[j]);
            W2b[j] = fmaf(-l1, a[j], W2b[j]);
        }
        b2a -= l0;
        b2b -= l1;

        // ---- dz = da * (z>0); update W1, b1 ----
        const float m0 = LRATE * k0;
        const float m1 = LRATE * k1;
        #pragma unroll
        for (int j = 0; j < INNER; ++j) {
            const float dz = (a[j] > 0.0f) ? p[j] : 0.0f;
            W1a[j] = fmaf(-m0, dz, W1a[j]);
            W1b[j] = fmaf(-m1, dz, W1b[j]);
            b1r[j] = fmaf(-LRATE, dz, b1r[j]);
        }
    }

    // ---- final forward with q = hs[:, L-1], then logits ----
    {
        const int tq = toks[LSEQ - 1];
        const float q0 = tab[tq * H + t];
        const float q1 = tab[tq * H + t + 32];
        #pragma unroll
        for (int j = 0; j < INNER; ++j)
            p[j] = fmaf(q0, W1a[j], q1 * W1b[j]);
        #pragma unroll
        for (int st = 16; st >= 1; st >>= 1) {
            #pragma unroll
            for (int j = 0; j < INNER; ++j)
                p[j] += __shfl_xor_sync(0xffffffffu, p[j], st);
        }
        #pragma unroll
        for (int j = 0; j < INNER; ++j)
            a[j] = fmaxf(p[j] + b1r[j], 0.0f);

        float c0 = b2a, c1 = b2b;
        #pragma unroll
        for (int j = 0; j < INNER; ++j) {
            c0 = fmaf(a[j], W2a[j], c0);
            c1 = fmaf(a[j], W2b[j], c1);
        }
        ctx_sh[t]      = c0;
        ctx_sh[t + 32] = c1;
    }
    __syncwarp();

    // out[b, o] = out_b[o] + sum_h ctx[h] * out_w[h, o];  lane handles o = t, t+32
    #pragma unroll
    for (int half = 0; half < 2; ++half) {
        const int o = t + half * 32;
        float acc = out_b[o];
        #pragma unroll 8
        for (int h = 0; h < H; ++h)
            acc = fmaf(ctx_sh[h], out_w[h * 64 + o], acc);
        out[b * 64 + o] = acc;
    }
}

// ---------------------------------------------------------------------------
// Launch
// Inputs (metadata order): 0 seq(i32), 1 embed, 2 ff_w1, 3 ff_b1, 4 ff_w2,
// 5 ff_b2, 6 ln_g, 7 ln_b, 8 w1, 9 b1, 10 w2, 11 b2, 12 out_w, 13 out_b
// ---------------------------------------------------------------------------
extern "C" void kernel_launch(void* const* d_in, const int* in_sizes, int n_in,
                              void* d_out, int out_size)
{
    const int*   seq    = (const int*)  d_in[0];
    const float* embed  = (const float*)d_in[1];
    const float* ff_w1  = (const float*)d_in[2];
    const float* ff_b1  = (const float*)d_in[3];
    const float* ff_w2  = (const float*)d_in[4];
    const float* ff_b2  = (const float*)d_in[5];
    const float* ln_g   = (const float*)d_in[6];
    const float* ln_b   = (const float*)d_in[7];
    const float* w1     = (const float*)d_in[8];
    const float* b1     = (const float*)d_in[9];
    const float* w2     = (const float*)d_in[10];
    const float* b2     = (const float*)d_in[11];
    const float* out_w  = (const float*)d_in[12];
    const float* out_b  = (const float*)d_in[13];
    float*       out    = (float*)d_out;

    build_table_kernel<<<64, 128>>>(embed, ff_w1, ff_b1, ff_w2, ff_b2, ln_g, ln_b);
    ttt_kernel<<<256, 32>>>(seq, w1, b1, w2, b2, out_w, out_b, out);
}